// round 16
// baseline (speedup 1.0000x reference)
#include <cuda_runtime.h>
#include <cuda_bf16.h>
#include <cstdint>

// ---------------------------------------------------------------------------
// SwinBasicBlock: out = 2 * (window_attention(LN(x)) + x), BCHW.
// MLP branch is dead code in the reference -> skipped.
// B=8, C=256, H=W=128, WS=8, NH=8, hd=32, SHIFT=4, M = 131072 rows.
// Pipeline: wconv | K1 (LN+roll+partition) | K23 persistent (QKV GEMM +
//           attention, cross-window prefetch) | K4E (proj GEMM BK=64,
//           3 CTAs/SM, single barrier per k-tile + epilogue).
// ---------------------------------------------------------------------------

#define Cdim 256
#define Hdim 128
#define Wdim 128
#define MROWS 131072
#define NWIN 2048
#define NSM 148

// Scratch (device globals; allocation APIs forbidden)
__device__ __nv_bfloat16 g_Y[MROWS * Cdim];       // LN output, bf16
__device__ __nv_bfloat16 g_O[MROWS * Cdim];       // attn out, bf16
__device__ __nv_bfloat16 g_WTq[768 * 256];        // w_qkv^T  [n][k]
__device__ __nv_bfloat16 g_WTp[256 * 256];        // w_proj^T [n][k]

// ------------------------------ PTX helpers --------------------------------
__device__ __forceinline__ void cp16(uint32_t dst, const void* src) {
    asm volatile("cp.async.cg.shared.global [%0], [%1], 16;\n"
                 :: "r"(dst), "l"(src));
}
__device__ __forceinline__ void cp_commit() {
    asm volatile("cp.async.commit_group;\n");
}
template <int N> __device__ __forceinline__ void cp_wait() {
    asm volatile("cp.async.wait_group %0;\n" :: "n"(N));
}
__device__ __forceinline__ void ldsm_x4(uint32_t r[4], uint32_t addr) {
    asm volatile("ldmatrix.sync.aligned.m8n8.x4.shared.b16 {%0,%1,%2,%3}, [%4];\n"
                 : "=r"(r[0]), "=r"(r[1]), "=r"(r[2]), "=r"(r[3]) : "r"(addr));
}
__device__ __forceinline__ void ldsm_x4_t(uint32_t r[4], uint32_t addr) {
    asm volatile("ldmatrix.sync.aligned.m8n8.x4.trans.shared.b16 {%0,%1,%2,%3}, [%4];\n"
                 : "=r"(r[0]), "=r"(r[1]), "=r"(r[2]), "=r"(r[3]) : "r"(addr));
}
__device__ __forceinline__ void mma_bf16(float c[4], const uint32_t a[4],
                                         uint32_t b0, uint32_t b1) {
    asm volatile(
        "mma.sync.aligned.m16n8k16.row.col.f32.bf16.bf16.f32 "
        "{%0,%1,%2,%3},{%4,%5,%6,%7},{%8,%9},{%0,%1,%2,%3};\n"
        : "+f"(c[0]), "+f"(c[1]), "+f"(c[2]), "+f"(c[3])
        : "r"(a[0]), "r"(a[1]), "r"(a[2]), "r"(a[3]), "r"(b0), "r"(b1));
}
__device__ __forceinline__ uint32_t packbf(float lo, float hi) {
    uint32_t r;
    asm("cvt.rn.bf16x2.f32 %0, %1, %2;\n" : "=r"(r) : "f"(hi), "f"(lo));
    return r;
}
__device__ __forceinline__ void sts32(uint32_t addr, uint32_t v) {
    asm volatile("st.shared.u32 [%0], %1;\n" :: "r"(addr), "r"(v));
}
__device__ __forceinline__ uint32_t s2u(const void* p) {
    return (uint32_t)__cvta_generic_to_shared(p);
}

// 64B-row swizzle (4 x 16B chunks per row) — proven conflict-free for LDSM
__device__ __forceinline__ uint32_t swzQ(int row, int ch) {
    return (uint32_t)(row * 64 + ((ch ^ ((row >> 1) & 3)) << 4));
}
// 512B-row swizzle (32 x 16B chunks per row)
__device__ __forceinline__ uint32_t swzA(int row, int ch) {
    return (uint32_t)(row * 512 + ((ch ^ (row & 7)) << 4));
}
// 128B-row swizzle (8 x 16B chunks per row)
__device__ __forceinline__ uint32_t swzB(int row, int ch) {
    return (uint32_t)(row * 128 + ((ch ^ (row & 7)) << 4));
}

// ---------------------------------------------------------------------------
// W0: transpose weights to [N][K] bf16.
// ---------------------------------------------------------------------------
__global__ void wconv(const float* __restrict__ wq, const float* __restrict__ wp) {
    const int idx = blockIdx.x * 256 + threadIdx.x;   // 768*256 threads
    const int n = idx >> 8, k = idx & 255;
    g_WTq[idx] = __float2bfloat16(wq[k * 768 + n]);
    if (n < 256) g_WTp[idx] = __float2bfloat16(wp[k * 256 + n]);
}

// ---------------------------------------------------------------------------
// K1: LayerNorm over C + cyclic shift (-4,-4) + window partition -> bf16 Y.
// (verbatim R14, proven: packed bf16x2 stores)
// ---------------------------------------------------------------------------
__global__ void k1_ln_roll_part(const float* __restrict__ x,
                                const float* __restrict__ gamma,
                                const float* __restrict__ beta,
                                __nv_bfloat16* __restrict__ Y) {
    __shared__ float tile[32][257];
    const int b  = blockIdx.z;
    const int h  = blockIdx.y;
    const int w0 = blockIdx.x * 32;
    const int t  = threadIdx.x;
    const int wl = t & 31;
    const int co = t >> 5;

    const float* xb = x + (long)b * Cdim * Hdim * Wdim;
    #pragma unroll
    for (int cb = 0; cb < Cdim; cb += 8) {
        const int c = cb + co;
        tile[wl][c] = xb[((long)c * Hdim + h) * Wdim + w0 + wl];
    }
    __syncthreads();

    const int p = t >> 3, sub = t & 7;
    float s = 0.f, ss = 0.f;
    #pragma unroll
    for (int c = sub; c < Cdim; c += 8) {
        const float v = tile[p][c];
        s += v; ss += v * v;
    }
    #pragma unroll
    for (int off = 4; off > 0; off >>= 1) {
        s  += __shfl_xor_sync(0xffffffffu, s,  off);
        ss += __shfl_xor_sync(0xffffffffu, ss, off);
    }
    const float mean = s * (1.f / Cdim);
    const float var  = ss * (1.f / Cdim) - mean * mean;
    const float inv  = rsqrtf(var + 1e-5f);
    #pragma unroll
    for (int c = sub; c < Cdim; c += 8)
        tile[p][c] = (tile[p][c] - mean) * inv * gamma[c] + beta[c];
    __syncthreads();

    const int h2  = (h - 4) & 127;
    const int p2h = t >> 7;
    const int tc  = t & 127;
    #pragma unroll 4
    for (int p2b = 0; p2b < 32; p2b += 2) {
        const int p2 = p2b + p2h;
        const int w2 = (w0 + p2 - 4) & 127;
        const long row = (((long)b * 16 + (h2 >> 3)) * 16 + (w2 >> 3)) * 64
                         + (h2 & 7) * 8 + (w2 & 7);
        *(uint32_t*)&Y[row * Cdim + 2 * tc] =
            packbf(tile[p2][2 * tc], tile[p2][2 * tc + 1]);
    }
}

// ---------------------------------------------------------------------------
// K23: persistent fused QKV GEMM + attention. (verbatim R15, proven)
// ---------------------------------------------------------------------------
#define RA   0
#define RC2  32768
#define RBS  131072
#define BS_CH 49152
#define K23_SMEM 229376

__global__ __launch_bounds__(512, 1)
void k23_qkv_attn(const __nv_bfloat16* __restrict__ Y,
                  const float* __restrict__ bqkv,
                  __nv_bfloat16* __restrict__ O) {
    extern __shared__ char smem[];
    const uint32_t sb = s2u(smem);
    const __nv_bfloat16* WTq = g_WTq;

    const int t    = threadIdx.x;
    const int wid  = t >> 5;
    const int lane = t & 31;
    const int gid  = lane >> 2;
    const int tig  = lane & 3;
    const int r16  = lane & 15;
    const int hs2  = lane >> 4;
    const int sel  = lane >> 3, l8 = lane & 7;

    auto loadA = [&](int win) {
        const __nv_bfloat16* src = Y + (long)win * 64 * 256;
        #pragma unroll
        for (int i = 0; i < 4; i++) {
            const int cid = i * 512 + t;
            const int row = cid >> 5, ch = cid & 31;
            cp16(sb + RA + swzA(row, ch), src + (long)row * 256 + ch * 8);
        }
    };

    auto loadB = [&](int q) {
        const int pass = q >> 2, kt = q & 3, buf = q & 1;
        const __nv_bfloat16* src = WTq + (long)pass * 384 * 256 + kt * 64;
        const uint32_t base = sb + RBS + buf * BS_CH;
        #pragma unroll
        for (int i = 0; i < 6; i++) {
            const int cid = i * 512 + t;
            const int n = cid >> 3, ch = cid & 7;
            cp16(base + swzB(n, ch), src + (long)n * 256 + ch * 8);
        }
    };

    const int w0 = blockIdx.x;
    const int wm   = (wid & 1) * 32;
    const int wcol = wid >> 1;
    const float scale = 0.17677669529663689f;

    if (w0 < NWIN) { loadA(w0); loadB(0); }
    cp_commit();

    for (int win = w0; win < NWIN; win += NSM) {
        float qa[2][6][4];
        #pragma unroll 1
        for (int q = 0; q < 8; q++) {
            const int pass = q >> 2, kt = q & 3, buf = q & 1;
            if (kt == 0) {
                #pragma unroll
                for (int a1 = 0; a1 < 2; a1++)
                    #pragma unroll
                    for (int a2 = 0; a2 < 6; a2++)
                        #pragma unroll
                        for (int a3 = 0; a3 < 4; a3++) qa[a1][a2][a3] = 0.f;
            }
            cp_wait<0>();
            __syncthreads();
            if (q + 1 < 8) { loadB(q + 1); cp_commit(); }

            const uint32_t bb0 = sb + RBS + buf * BS_CH;
            #pragma unroll
            for (int ks = 0; ks < 4; ks++) {
                uint32_t af[2][4];
                #pragma unroll
                for (int mt = 0; mt < 2; mt++)
                    ldsm_x4(af[mt], sb + RA + swzA(wm + mt * 16 + r16,
                                                   kt * 8 + ks * 2 + hs2));
                #pragma unroll
                for (int np = 0; np < 3; np++) {
                    const int brow = wcol * 48 + np * 16 + ((sel & 2) ? 8 : 0) + l8;
                    uint32_t bf[4];
                    ldsm_x4(bf, bb0 + swzB(brow, ks * 2 + (sel & 1)));
                    #pragma unroll
                    for (int mt = 0; mt < 2; mt++) {
                        mma_bf16(qa[mt][np * 2],     af[mt], bf[0], bf[1]);
                        mma_bf16(qa[mt][np * 2 + 1], af[mt], bf[2], bf[3]);
                    }
                }
            }

            if (kt == 3) {
                #pragma unroll
                for (int nt = 0; nt < 6; nt++) {
                    const int col = pass * 384 + wcol * 48 + nt * 8 + tig * 2;
                    const float bq0 = bqkv[col], bq1 = bqkv[col + 1];
                    const int qkvi = col >> 8;
                    const int head = (col >> 5) & 7;
                    const int wi   = col & 31;
                    const uint32_t tb = sb + RC2 + (qkvi * 8 + head) * 4096;
                    #pragma unroll
                    for (int mt = 0; mt < 2; mt++) {
                        const int r0 = wm + mt * 16 + gid;
                        sts32(tb + swzQ(r0, wi >> 3) + (wi & 7) * 2,
                              packbf(qa[mt][nt][0] + bq0, qa[mt][nt][1] + bq1));
                        sts32(tb + swzQ(r0 + 8, wi >> 3) + (wi & 7) * 2,
                              packbf(qa[mt][nt][2] + bq0, qa[mt][nt][3] + bq1));
                    }
                }
            }
        }
        __syncthreads();

        if (win + NSM < NWIN) { loadA(win + NSM); loadB(0); cp_commit(); }

        {
            const int head = wid >> 1;
            const int mb   = (wid & 1) * 32;
            const uint32_t qb = sb + RC2 + head * 4096;
            const uint32_t kb = sb + RC2 + (8 + head) * 4096;
            const uint32_t vb = sb + RC2 + (16 + head) * 4096;

            float sc[2][8][4];
            #pragma unroll
            for (int mt = 0; mt < 2; mt++)
                #pragma unroll
                for (int nt = 0; nt < 8; nt++)
                    #pragma unroll
                    for (int r = 0; r < 4; r++) sc[mt][nt][r] = 0.f;

            #pragma unroll
            for (int ks = 0; ks < 2; ks++) {
                uint32_t af[2][4];
                #pragma unroll
                for (int mt = 0; mt < 2; mt++)
                    ldsm_x4(af[mt], qb + swzQ(mb + mt * 16 + r16, ks * 2 + hs2));
                #pragma unroll
                for (int np = 0; np < 4; np++) {
                    const int brow = np * 16 + ((sel & 2) ? 8 : 0) + l8;
                    uint32_t bf[4];
                    ldsm_x4(bf, kb + swzQ(brow, ks * 2 + (sel & 1)));
                    #pragma unroll
                    for (int mt = 0; mt < 2; mt++) {
                        mma_bf16(sc[mt][np * 2],     af[mt], bf[0], bf[1]);
                        mma_bf16(sc[mt][np * 2 + 1], af[mt], bf[2], bf[3]);
                    }
                }
            }

            float ilo[2], ihi[2];
            #pragma unroll
            for (int mt = 0; mt < 2; mt++) {
                float mlo = -1e30f, mhi = -1e30f;
                #pragma unroll
                for (int nt = 0; nt < 8; nt++) {
                    mlo = fmaxf(mlo, fmaxf(sc[mt][nt][0], sc[mt][nt][1]));
                    mhi = fmaxf(mhi, fmaxf(sc[mt][nt][2], sc[mt][nt][3]));
                }
                mlo = fmaxf(mlo, __shfl_xor_sync(0xffffffffu, mlo, 1));
                mlo = fmaxf(mlo, __shfl_xor_sync(0xffffffffu, mlo, 2));
                mhi = fmaxf(mhi, __shfl_xor_sync(0xffffffffu, mhi, 1));
                mhi = fmaxf(mhi, __shfl_xor_sync(0xffffffffu, mhi, 2));
                float slo = 0.f, shi = 0.f;
                #pragma unroll
                for (int nt = 0; nt < 8; nt++) {
                    sc[mt][nt][0] = __expf(scale * (sc[mt][nt][0] - mlo));
                    sc[mt][nt][1] = __expf(scale * (sc[mt][nt][1] - mlo));
                    sc[mt][nt][2] = __expf(scale * (sc[mt][nt][2] - mhi));
                    sc[mt][nt][3] = __expf(scale * (sc[mt][nt][3] - mhi));
                    slo += sc[mt][nt][0] + sc[mt][nt][1];
                    shi += sc[mt][nt][2] + sc[mt][nt][3];
                }
                slo += __shfl_xor_sync(0xffffffffu, slo, 1);
                slo += __shfl_xor_sync(0xffffffffu, slo, 2);
                shi += __shfl_xor_sync(0xffffffffu, shi, 1);
                shi += __shfl_xor_sync(0xffffffffu, shi, 2);
                ilo[mt] = 1.f / slo;
                ihi[mt] = 1.f / shi;
            }

            float oc[2][4][4];
            #pragma unroll
            for (int mt = 0; mt < 2; mt++)
                #pragma unroll
                for (int nt = 0; nt < 4; nt++)
                    #pragma unroll
                    for (int r = 0; r < 4; r++) oc[mt][nt][r] = 0.f;

            #pragma unroll
            for (int ks = 0; ks < 4; ks++) {
                uint32_t pa[2][4];
                #pragma unroll
                for (int mt = 0; mt < 2; mt++) {
                    pa[mt][0] = packbf(sc[mt][2*ks][0] * ilo[mt], sc[mt][2*ks][1] * ilo[mt]);
                    pa[mt][1] = packbf(sc[mt][2*ks][2] * ihi[mt], sc[mt][2*ks][3] * ihi[mt]);
                    pa[mt][2] = packbf(sc[mt][2*ks+1][0] * ilo[mt], sc[mt][2*ks+1][1] * ilo[mt]);
                    pa[mt][3] = packbf(sc[mt][2*ks+1][2] * ihi[mt], sc[mt][2*ks+1][3] * ihi[mt]);
                }
                #pragma unroll
                for (int dp = 0; dp < 2; dp++) {
                    const int vrow = ks * 16 + ((sel & 1) ? 8 : 0) + l8;
                    uint32_t vf[4];
                    ldsm_x4_t(vf, vb + swzQ(vrow, dp * 2 + ((sel & 2) >> 1)));
                    #pragma unroll
                    for (int mt = 0; mt < 2; mt++) {
                        mma_bf16(oc[mt][dp * 2],     pa[mt], vf[0], vf[1]);
                        mma_bf16(oc[mt][dp * 2 + 1], pa[mt], vf[2], vf[3]);
                    }
                }
            }

            #pragma unroll
            for (int mt = 0; mt < 2; mt++) {
                const long row = (long)win * 64 + mb + mt * 16 + gid;
                #pragma unroll
                for (int nt = 0; nt < 4; nt++) {
                    const int col = head * 32 + nt * 8 + 2 * tig;
                    *(uint32_t*)&O[row * 256 + col] =
                        packbf(oc[mt][nt][0], oc[mt][nt][1]);
                    *(uint32_t*)&O[(row + 8) * 256 + col] =
                        packbf(oc[mt][nt][2], oc[mt][nt][3]);
                }
            }
        }
    }
}

// ---------------------------------------------------------------------------
// K4E: proj GEMM (BK=64) + epilogue. 3 CTAs/SM via launch bounds; one
// barrier per k-tile (trailing sync removed — next iteration's post-wait
// barrier orders stage reuse).
// ---------------------------------------------------------------------------
#define GPP 72
#define K4E_STAGE (128 * GPP)

__global__ __launch_bounds__(256, 3)
void bf16_gemm_proj_epi(const __nv_bfloat16* __restrict__ A,
                        const __nv_bfloat16* __restrict__ WT,
                        const float* __restrict__ bias,
                        const float* __restrict__ x,
                        float* __restrict__ out) {
    extern __shared__ __nv_bfloat16 dsm[];
    const int K = 256;

    const int t    = threadIdx.x;
    const int warp = t >> 5;
    const int lane = t & 31;
    const int gid  = lane >> 2;
    const int tig  = lane & 3;
    const int wm   = (warp >> 2) * 64;
    const int wn   = (warp & 3) * 32;
    const int bm   = blockIdx.y * 128;
    const int bn   = blockIdx.x * 128;

    const uint32_t asb = s2u(dsm);
    const uint32_t bsb = asb + 2 * K4E_STAGE * 2;

    auto loadStage = [&](int st, int k0) {
        #pragma unroll
        for (int i = 0; i < 4; i++) {
            const int ci  = t + i * 256;
            const int row = ci >> 3;
            const int kc  = (ci & 7) * 8;
            cp16(asb + (st * K4E_STAGE + row * GPP + kc) * 2,
                 A + (long)(bm + row) * K + k0 + kc);
            cp16(bsb + (st * K4E_STAGE + row * GPP + kc) * 2,
                 WT + (long)(bn + row) * K + k0 + kc);
        }
        cp_commit();
    };

    float acc[4][4][4];
    #pragma unroll
    for (int i = 0; i < 4; i++)
        #pragma unroll
        for (int j = 0; j < 4; j++)
            #pragma unroll
            for (int r = 0; r < 4; r++) acc[i][j][r] = 0.f;

    loadStage(0, 0);

    const int r16  = lane & 15;
    const int hsel = (lane >> 4) << 3;
    const int sel  = lane >> 3, l8 = lane & 7;

    #pragma unroll 1
    for (int kt = 0; kt < 4; kt++) {
        cp_wait<0>();
        __syncthreads();
        if (kt + 1 < 4) loadStage((kt + 1) & 1, (kt + 1) * 64);

        const int st = kt & 1;
        #pragma unroll
        for (int ks = 0; ks < 4; ks++) {
            uint32_t af[4][4];
            #pragma unroll
            for (int mt = 0; mt < 4; mt++)
                ldsm_x4(af[mt], asb + (st * K4E_STAGE
                        + (wm + mt * 16 + r16) * GPP + ks * 16 + hsel) * 2);
            #pragma unroll
            for (int np = 0; np < 2; np++) {
                const int brow = wn + np * 16 + ((sel & 2) ? 8 : 0) + l8;
                const int bcol = ks * 16 + ((sel & 1) ? 8 : 0);
                uint32_t bf[4];
                ldsm_x4(bf, bsb + (st * K4E_STAGE + brow * GPP + bcol) * 2);
                #pragma unroll
                for (int mt = 0; mt < 4; mt++) {
                    mma_bf16(acc[mt][np * 2],     af[mt], bf[0], bf[1]);
                    mma_bf16(acc[mt][np * 2 + 1], af[mt], bf[2], bf[3]);
                }
            }
        }
        // no trailing barrier: next iteration's post-wait barrier orders reuse
    }

    #pragma unroll
    for (int mt = 0; mt < 4; mt++) {
        #pragma unroll
        for (int rh = 0; rh < 2; rh++) {
            const int row = bm + wm + mt * 16 + gid + rh * 8;
            const int win = row >> 6;
            const int n   = row & 63;
            const int b   = win >> 8;
            const int wh  = (win >> 4) & 15;
            const int ww  = win & 15;
            const int h   = (wh * 8 + (n >> 3) + 4) & 127;
            const int w   = (ww * 8 + (n & 7) + 4) & 127;
            const long pbase = ((long)b * Cdim) * (Hdim * Wdim) + h * Wdim + w;
            #pragma unroll
            for (int nt = 0; nt < 4; nt++) {
                const int c0 = bn + wn + nt * 8 + 2 * tig;
                const long i0 = pbase + (long)c0 * (Hdim * Wdim);
                const long i1 = i0 + (Hdim * Wdim);
                out[i0] = 2.f * (acc[mt][nt][rh * 2]     + bias[c0]     + x[i0]);
                out[i1] = 2.f * (acc[mt][nt][rh * 2 + 1] + bias[c0 + 1] + x[i1]);
            }
        }
    }
}

// ---------------------------------------------------------------------------
extern "C" void kernel_launch(void* const* d_in, const int* in_sizes, int n_in,
                              void* d_out, int out_size) {
    const float* x      = (const float*)d_in[0];
    const float* n1g    = (const float*)d_in[1];
    const float* n1b    = (const float*)d_in[2];
    const float* w_qkv  = (const float*)d_in[3];
    const float* b_qkv  = (const float*)d_in[4];
    const float* w_proj = (const float*)d_in[5];
    const float* b_proj = (const float*)d_in[6];
    float* out = (float*)d_out;

    __nv_bfloat16 *Y, *Obuf, *WTp;
    cudaGetSymbolAddress((void**)&Y,    g_Y);
    cudaGetSymbolAddress((void**)&Obuf, g_O);
    cudaGetSymbolAddress((void**)&WTp,  g_WTp);

    cudaFuncSetAttribute(k23_qkv_attn,
                         cudaFuncAttributeMaxDynamicSharedMemorySize, K23_SMEM);
    const int k4e_smem = 2 * 2 * K4E_STAGE * 2;   // 73728 B per CTA
    cudaFuncSetAttribute(bf16_gemm_proj_epi,
                         cudaFuncAttributeMaxDynamicSharedMemorySize, k4e_smem);

    // W0: weight transpose+convert
    wconv<<<768, 256>>>(w_qkv, w_proj);

    // K1: LN + shift + window partition -> bf16 (packed stores)
    k1_ln_roll_part<<<dim3(4, 128, 8), 256>>>(x, n1g, n1b, Y);

    // K23: persistent fused QKV GEMM + attention with cross-window prefetch
    k23_qkv_attn<<<NSM, 512, K23_SMEM>>>(Y, b_qkv, Obuf);

    // K4E: proj GEMM (BK=64, 3 CTAs/SM) + fused epilogue
    bf16_gemm_proj_epi<<<dim3(2, 1024), 256, k4e_smem>>>(Obuf, WTp, b_proj, x, out);
}

// round 17
// speedup vs baseline: 1.1885x; 1.1885x over previous
#include <cuda_runtime.h>
#include <cuda_bf16.h>
#include <cstdint>

// ---------------------------------------------------------------------------
// SwinBasicBlock: out = 2 * (window_attention(LN(x)) + x), BCHW.
// MLP branch is dead code in the reference -> skipped.
// B=8, C=256, H=W=128, WS=8, NH=8, hd=32, SHIFT=4, M = 131072 rows.
// Pipeline: wconv | K1 (LN+roll+partition) | K23 persistent (QKV GEMM +
//           attention, cross-window prefetch) | K4E (proj GEMM BK=64,
//           single barrier per k-tile + epilogue).
// ---------------------------------------------------------------------------

#define Cdim 256
#define Hdim 128
#define Wdim 128
#define MROWS 131072
#define NWIN 2048
#define NSM 148

// Scratch (device globals; allocation APIs forbidden)
__device__ __nv_bfloat16 g_Y[MROWS * Cdim];       // LN output, bf16
__device__ __nv_bfloat16 g_O[MROWS * Cdim];       // attn out, bf16
__device__ __nv_bfloat16 g_WTq[768 * 256];        // w_qkv^T  [n][k]
__device__ __nv_bfloat16 g_WTp[256 * 256];        // w_proj^T [n][k]

// ------------------------------ PTX helpers --------------------------------
__device__ __forceinline__ void cp16(uint32_t dst, const void* src) {
    asm volatile("cp.async.cg.shared.global [%0], [%1], 16;\n"
                 :: "r"(dst), "l"(src));
}
__device__ __forceinline__ void cp_commit() {
    asm volatile("cp.async.commit_group;\n");
}
template <int N> __device__ __forceinline__ void cp_wait() {
    asm volatile("cp.async.wait_group %0;\n" :: "n"(N));
}
__device__ __forceinline__ void ldsm_x4(uint32_t r[4], uint32_t addr) {
    asm volatile("ldmatrix.sync.aligned.m8n8.x4.shared.b16 {%0,%1,%2,%3}, [%4];\n"
                 : "=r"(r[0]), "=r"(r[1]), "=r"(r[2]), "=r"(r[3]) : "r"(addr));
}
__device__ __forceinline__ void ldsm_x4_t(uint32_t r[4], uint32_t addr) {
    asm volatile("ldmatrix.sync.aligned.m8n8.x4.trans.shared.b16 {%0,%1,%2,%3}, [%4];\n"
                 : "=r"(r[0]), "=r"(r[1]), "=r"(r[2]), "=r"(r[3]) : "r"(addr));
}
__device__ __forceinline__ void mma_bf16(float c[4], const uint32_t a[4],
                                         uint32_t b0, uint32_t b1) {
    asm volatile(
        "mma.sync.aligned.m16n8k16.row.col.f32.bf16.bf16.f32 "
        "{%0,%1,%2,%3},{%4,%5,%6,%7},{%8,%9},{%0,%1,%2,%3};\n"
        : "+f"(c[0]), "+f"(c[1]), "+f"(c[2]), "+f"(c[3])
        : "r"(a[0]), "r"(a[1]), "r"(a[2]), "r"(a[3]), "r"(b0), "r"(b1));
}
__device__ __forceinline__ uint32_t packbf(float lo, float hi) {
    uint32_t r;
    asm("cvt.rn.bf16x2.f32 %0, %1, %2;\n" : "=r"(r) : "f"(hi), "f"(lo));
    return r;
}
__device__ __forceinline__ void sts32(uint32_t addr, uint32_t v) {
    asm volatile("st.shared.u32 [%0], %1;\n" :: "r"(addr), "r"(v));
}
__device__ __forceinline__ uint32_t s2u(const void* p) {
    return (uint32_t)__cvta_generic_to_shared(p);
}

// 64B-row swizzle (4 x 16B chunks per row) — proven conflict-free for LDSM
__device__ __forceinline__ uint32_t swzQ(int row, int ch) {
    return (uint32_t)(row * 64 + ((ch ^ ((row >> 1) & 3)) << 4));
}
// 512B-row swizzle (32 x 16B chunks per row)
__device__ __forceinline__ uint32_t swzA(int row, int ch) {
    return (uint32_t)(row * 512 + ((ch ^ (row & 7)) << 4));
}
// 128B-row swizzle (8 x 16B chunks per row)
__device__ __forceinline__ uint32_t swzB(int row, int ch) {
    return (uint32_t)(row * 128 + ((ch ^ (row & 7)) << 4));
}

// ---------------------------------------------------------------------------
// W0: transpose weights to [N][K] bf16.
// ---------------------------------------------------------------------------
__global__ void wconv(const float* __restrict__ wq, const float* __restrict__ wp) {
    const int idx = blockIdx.x * 256 + threadIdx.x;   // 768*256 threads
    const int n = idx >> 8, k = idx & 255;
    g_WTq[idx] = __float2bfloat16(wq[k * 768 + n]);
    if (n < 256) g_WTp[idx] = __float2bfloat16(wp[k * 256 + n]);
}

// ---------------------------------------------------------------------------
// K1: LayerNorm over C + cyclic shift (-4,-4) + window partition -> bf16 Y.
// (verbatim R14, proven: packed bf16x2 stores)
// ---------------------------------------------------------------------------
__global__ void k1_ln_roll_part(const float* __restrict__ x,
                                const float* __restrict__ gamma,
                                const float* __restrict__ beta,
                                __nv_bfloat16* __restrict__ Y) {
    __shared__ float tile[32][257];
    const int b  = blockIdx.z;
    const int h  = blockIdx.y;
    const int w0 = blockIdx.x * 32;
    const int t  = threadIdx.x;
    const int wl = t & 31;
    const int co = t >> 5;

    const float* xb = x + (long)b * Cdim * Hdim * Wdim;
    #pragma unroll
    for (int cb = 0; cb < Cdim; cb += 8) {
        const int c = cb + co;
        tile[wl][c] = xb[((long)c * Hdim + h) * Wdim + w0 + wl];
    }
    __syncthreads();

    const int p = t >> 3, sub = t & 7;
    float s = 0.f, ss = 0.f;
    #pragma unroll
    for (int c = sub; c < Cdim; c += 8) {
        const float v = tile[p][c];
        s += v; ss += v * v;
    }
    #pragma unroll
    for (int off = 4; off > 0; off >>= 1) {
        s  += __shfl_xor_sync(0xffffffffu, s,  off);
        ss += __shfl_xor_sync(0xffffffffu, ss, off);
    }
    const float mean = s * (1.f / Cdim);
    const float var  = ss * (1.f / Cdim) - mean * mean;
    const float inv  = rsqrtf(var + 1e-5f);
    #pragma unroll
    for (int c = sub; c < Cdim; c += 8)
        tile[p][c] = (tile[p][c] - mean) * inv * gamma[c] + beta[c];
    __syncthreads();

    const int h2  = (h - 4) & 127;
    const int p2h = t >> 7;
    const int tc  = t & 127;
    #pragma unroll 4
    for (int p2b = 0; p2b < 32; p2b += 2) {
        const int p2 = p2b + p2h;
        const int w2 = (w0 + p2 - 4) & 127;
        const long row = (((long)b * 16 + (h2 >> 3)) * 16 + (w2 >> 3)) * 64
                         + (h2 & 7) * 8 + (w2 & 7);
        *(uint32_t*)&Y[row * Cdim + 2 * tc] =
            packbf(tile[p2][2 * tc], tile[p2][2 * tc + 1]);
    }
}

// ---------------------------------------------------------------------------
// K23: persistent fused QKV GEMM + attention. (verbatim R15, proven)
// ---------------------------------------------------------------------------
#define RA   0
#define RC2  32768
#define RBS  131072
#define BS_CH 49152
#define K23_SMEM 229376

__global__ __launch_bounds__(512, 1)
void k23_qkv_attn(const __nv_bfloat16* __restrict__ Y,
                  const float* __restrict__ bqkv,
                  __nv_bfloat16* __restrict__ O) {
    extern __shared__ char smem[];
    const uint32_t sb = s2u(smem);
    const __nv_bfloat16* WTq = g_WTq;

    const int t    = threadIdx.x;
    const int wid  = t >> 5;
    const int lane = t & 31;
    const int gid  = lane >> 2;
    const int tig  = lane & 3;
    const int r16  = lane & 15;
    const int hs2  = lane >> 4;
    const int sel  = lane >> 3, l8 = lane & 7;

    auto loadA = [&](int win) {
        const __nv_bfloat16* src = Y + (long)win * 64 * 256;
        #pragma unroll
        for (int i = 0; i < 4; i++) {
            const int cid = i * 512 + t;
            const int row = cid >> 5, ch = cid & 31;
            cp16(sb + RA + swzA(row, ch), src + (long)row * 256 + ch * 8);
        }
    };

    auto loadB = [&](int q) {
        const int pass = q >> 2, kt = q & 3, buf = q & 1;
        const __nv_bfloat16* src = WTq + (long)pass * 384 * 256 + kt * 64;
        const uint32_t base = sb + RBS + buf * BS_CH;
        #pragma unroll
        for (int i = 0; i < 6; i++) {
            const int cid = i * 512 + t;
            const int n = cid >> 3, ch = cid & 7;
            cp16(base + swzB(n, ch), src + (long)n * 256 + ch * 8);
        }
    };

    const int w0 = blockIdx.x;
    const int wm   = (wid & 1) * 32;
    const int wcol = wid >> 1;
    const float scale = 0.17677669529663689f;

    if (w0 < NWIN) { loadA(w0); loadB(0); }
    cp_commit();

    for (int win = w0; win < NWIN; win += NSM) {
        float qa[2][6][4];
        #pragma unroll 1
        for (int q = 0; q < 8; q++) {
            const int pass = q >> 2, kt = q & 3, buf = q & 1;
            if (kt == 0) {
                #pragma unroll
                for (int a1 = 0; a1 < 2; a1++)
                    #pragma unroll
                    for (int a2 = 0; a2 < 6; a2++)
                        #pragma unroll
                        for (int a3 = 0; a3 < 4; a3++) qa[a1][a2][a3] = 0.f;
            }
            cp_wait<0>();
            __syncthreads();
            if (q + 1 < 8) { loadB(q + 1); cp_commit(); }

            const uint32_t bb0 = sb + RBS + buf * BS_CH;
            #pragma unroll
            for (int ks = 0; ks < 4; ks++) {
                uint32_t af[2][4];
                #pragma unroll
                for (int mt = 0; mt < 2; mt++)
                    ldsm_x4(af[mt], sb + RA + swzA(wm + mt * 16 + r16,
                                                   kt * 8 + ks * 2 + hs2));
                #pragma unroll
                for (int np = 0; np < 3; np++) {
                    const int brow = wcol * 48 + np * 16 + ((sel & 2) ? 8 : 0) + l8;
                    uint32_t bf[4];
                    ldsm_x4(bf, bb0 + swzB(brow, ks * 2 + (sel & 1)));
                    #pragma unroll
                    for (int mt = 0; mt < 2; mt++) {
                        mma_bf16(qa[mt][np * 2],     af[mt], bf[0], bf[1]);
                        mma_bf16(qa[mt][np * 2 + 1], af[mt], bf[2], bf[3]);
                    }
                }
            }

            if (kt == 3) {
                #pragma unroll
                for (int nt = 0; nt < 6; nt++) {
                    const int col = pass * 384 + wcol * 48 + nt * 8 + tig * 2;
                    const float bq0 = bqkv[col], bq1 = bqkv[col + 1];
                    const int qkvi = col >> 8;
                    const int head = (col >> 5) & 7;
                    const int wi   = col & 31;
                    const uint32_t tb = sb + RC2 + (qkvi * 8 + head) * 4096;
                    #pragma unroll
                    for (int mt = 0; mt < 2; mt++) {
                        const int r0 = wm + mt * 16 + gid;
                        sts32(tb + swzQ(r0, wi >> 3) + (wi & 7) * 2,
                              packbf(qa[mt][nt][0] + bq0, qa[mt][nt][1] + bq1));
                        sts32(tb + swzQ(r0 + 8, wi >> 3) + (wi & 7) * 2,
                              packbf(qa[mt][nt][2] + bq0, qa[mt][nt][3] + bq1));
                    }
                }
            }
        }
        __syncthreads();

        if (win + NSM < NWIN) { loadA(win + NSM); loadB(0); cp_commit(); }

        {
            const int head = wid >> 1;
            const int mb   = (wid & 1) * 32;
            const uint32_t qb = sb + RC2 + head * 4096;
            const uint32_t kb = sb + RC2 + (8 + head) * 4096;
            const uint32_t vb = sb + RC2 + (16 + head) * 4096;

            float sc[2][8][4];
            #pragma unroll
            for (int mt = 0; mt < 2; mt++)
                #pragma unroll
                for (int nt = 0; nt < 8; nt++)
                    #pragma unroll
                    for (int r = 0; r < 4; r++) sc[mt][nt][r] = 0.f;

            #pragma unroll
            for (int ks = 0; ks < 2; ks++) {
                uint32_t af[2][4];
                #pragma unroll
                for (int mt = 0; mt < 2; mt++)
                    ldsm_x4(af[mt], qb + swzQ(mb + mt * 16 + r16, ks * 2 + hs2));
                #pragma unroll
                for (int np = 0; np < 4; np++) {
                    const int brow = np * 16 + ((sel & 2) ? 8 : 0) + l8;
                    uint32_t bf[4];
                    ldsm_x4(bf, kb + swzQ(brow, ks * 2 + (sel & 1)));
                    #pragma unroll
                    for (int mt = 0; mt < 2; mt++) {
                        mma_bf16(sc[mt][np * 2],     af[mt], bf[0], bf[1]);
                        mma_bf16(sc[mt][np * 2 + 1], af[mt], bf[2], bf[3]);
                    }
                }
            }

            float ilo[2], ihi[2];
            #pragma unroll
            for (int mt = 0; mt < 2; mt++) {
                float mlo = -1e30f, mhi = -1e30f;
                #pragma unroll
                for (int nt = 0; nt < 8; nt++) {
                    mlo = fmaxf(mlo, fmaxf(sc[mt][nt][0], sc[mt][nt][1]));
                    mhi = fmaxf(mhi, fmaxf(sc[mt][nt][2], sc[mt][nt][3]));
                }
                mlo = fmaxf(mlo, __shfl_xor_sync(0xffffffffu, mlo, 1));
                mlo = fmaxf(mlo, __shfl_xor_sync(0xffffffffu, mlo, 2));
                mhi = fmaxf(mhi, __shfl_xor_sync(0xffffffffu, mhi, 1));
                mhi = fmaxf(mhi, __shfl_xor_sync(0xffffffffu, mhi, 2));
                float slo = 0.f, shi = 0.f;
                #pragma unroll
                for (int nt = 0; nt < 8; nt++) {
                    sc[mt][nt][0] = __expf(scale * (sc[mt][nt][0] - mlo));
                    sc[mt][nt][1] = __expf(scale * (sc[mt][nt][1] - mlo));
                    sc[mt][nt][2] = __expf(scale * (sc[mt][nt][2] - mhi));
                    sc[mt][nt][3] = __expf(scale * (sc[mt][nt][3] - mhi));
                    slo += sc[mt][nt][0] + sc[mt][nt][1];
                    shi += sc[mt][nt][2] + sc[mt][nt][3];
                }
                slo += __shfl_xor_sync(0xffffffffu, slo, 1);
                slo += __shfl_xor_sync(0xffffffffu, slo, 2);
                shi += __shfl_xor_sync(0xffffffffu, shi, 1);
                shi += __shfl_xor_sync(0xffffffffu, shi, 2);
                ilo[mt] = 1.f / slo;
                ihi[mt] = 1.f / shi;
            }

            float oc[2][4][4];
            #pragma unroll
            for (int mt = 0; mt < 2; mt++)
                #pragma unroll
                for (int nt = 0; nt < 4; nt++)
                    #pragma unroll
                    for (int r = 0; r < 4; r++) oc[mt][nt][r] = 0.f;

            #pragma unroll
            for (int ks = 0; ks < 4; ks++) {
                uint32_t pa[2][4];
                #pragma unroll
                for (int mt = 0; mt < 2; mt++) {
                    pa[mt][0] = packbf(sc[mt][2*ks][0] * ilo[mt], sc[mt][2*ks][1] * ilo[mt]);
                    pa[mt][1] = packbf(sc[mt][2*ks][2] * ihi[mt], sc[mt][2*ks][3] * ihi[mt]);
                    pa[mt][2] = packbf(sc[mt][2*ks+1][0] * ilo[mt], sc[mt][2*ks+1][1] * ilo[mt]);
                    pa[mt][3] = packbf(sc[mt][2*ks+1][2] * ihi[mt], sc[mt][2*ks+1][3] * ihi[mt]);
                }
                #pragma unroll
                for (int dp = 0; dp < 2; dp++) {
                    const int vrow = ks * 16 + ((sel & 1) ? 8 : 0) + l8;
                    uint32_t vf[4];
                    ldsm_x4_t(vf, vb + swzQ(vrow, dp * 2 + ((sel & 2) >> 1)));
                    #pragma unroll
                    for (int mt = 0; mt < 2; mt++) {
                        mma_bf16(oc[mt][dp * 2],     pa[mt], vf[0], vf[1]);
                        mma_bf16(oc[mt][dp * 2 + 1], pa[mt], vf[2], vf[3]);
                    }
                }
            }

            #pragma unroll
            for (int mt = 0; mt < 2; mt++) {
                const long row = (long)win * 64 + mb + mt * 16 + gid;
                #pragma unroll
                for (int nt = 0; nt < 4; nt++) {
                    const int col = head * 32 + nt * 8 + 2 * tig;
                    *(uint32_t*)&O[row * 256 + col] =
                        packbf(oc[mt][nt][0], oc[mt][nt][1]);
                    *(uint32_t*)&O[(row + 8) * 256 + col] =
                        packbf(oc[mt][nt][2], oc[mt][nt][3]);
                }
            }
        }
    }
}

// ---------------------------------------------------------------------------
// K4E: proj GEMM (BK=64) + epilogue. Default regs (102, 2 CTAs/SM — no spill);
// one barrier per k-tile (next iteration's post-wait barrier orders reuse).
// ---------------------------------------------------------------------------
#define GPP 72
#define K4E_STAGE (128 * GPP)

__global__ __launch_bounds__(256)
void bf16_gemm_proj_epi(const __nv_bfloat16* __restrict__ A,
                        const __nv_bfloat16* __restrict__ WT,
                        const float* __restrict__ bias,
                        const float* __restrict__ x,
                        float* __restrict__ out) {
    extern __shared__ __nv_bfloat16 dsm[];
    const int K = 256;

    const int t    = threadIdx.x;
    const int warp = t >> 5;
    const int lane = t & 31;
    const int gid  = lane >> 2;
    const int tig  = lane & 3;
    const int wm   = (warp >> 2) * 64;
    const int wn   = (warp & 3) * 32;
    const int bm   = blockIdx.y * 128;
    const int bn   = blockIdx.x * 128;

    const uint32_t asb = s2u(dsm);
    const uint32_t bsb = asb + 2 * K4E_STAGE * 2;

    auto loadStage = [&](int st, int k0) {
        #pragma unroll
        for (int i = 0; i < 4; i++) {
            const int ci  = t + i * 256;
            const int row = ci >> 3;
            const int kc  = (ci & 7) * 8;
            cp16(asb + (st * K4E_STAGE + row * GPP + kc) * 2,
                 A + (long)(bm + row) * K + k0 + kc);
            cp16(bsb + (st * K4E_STAGE + row * GPP + kc) * 2,
                 WT + (long)(bn + row) * K + k0 + kc);
        }
        cp_commit();
    };

    float acc[4][4][4];
    #pragma unroll
    for (int i = 0; i < 4; i++)
        #pragma unroll
        for (int j = 0; j < 4; j++)
            #pragma unroll
            for (int r = 0; r < 4; r++) acc[i][j][r] = 0.f;

    loadStage(0, 0);

    const int r16  = lane & 15;
    const int hsel = (lane >> 4) << 3;
    const int sel  = lane >> 3, l8 = lane & 7;

    #pragma unroll 1
    for (int kt = 0; kt < 4; kt++) {
        cp_wait<0>();
        __syncthreads();
        if (kt + 1 < 4) loadStage((kt + 1) & 1, (kt + 1) * 64);

        const int st = kt & 1;
        #pragma unroll
        for (int ks = 0; ks < 4; ks++) {
            uint32_t af[4][4];
            #pragma unroll
            for (int mt = 0; mt < 4; mt++)
                ldsm_x4(af[mt], asb + (st * K4E_STAGE
                        + (wm + mt * 16 + r16) * GPP + ks * 16 + hsel) * 2);
            #pragma unroll
            for (int np = 0; np < 2; np++) {
                const int brow = wn + np * 16 + ((sel & 2) ? 8 : 0) + l8;
                const int bcol = ks * 16 + ((sel & 1) ? 8 : 0);
                uint32_t bf[4];
                ldsm_x4(bf, bsb + (st * K4E_STAGE + brow * GPP + bcol) * 2);
                #pragma unroll
                for (int mt = 0; mt < 4; mt++) {
                    mma_bf16(acc[mt][np * 2],     af[mt], bf[0], bf[1]);
                    mma_bf16(acc[mt][np * 2 + 1], af[mt], bf[2], bf[3]);
                }
            }
        }
        // no trailing barrier: next iteration's post-wait barrier orders reuse
    }

    #pragma unroll
    for (int mt = 0; mt < 4; mt++) {
        #pragma unroll
        for (int rh = 0; rh < 2; rh++) {
            const int row = bm + wm + mt * 16 + gid + rh * 8;
            const int win = row >> 6;
            const int n   = row & 63;
            const int b   = win >> 8;
            const int wh  = (win >> 4) & 15;
            const int ww  = win & 15;
            const int h   = (wh * 8 + (n >> 3) + 4) & 127;
            const int w   = (ww * 8 + (n & 7) + 4) & 127;
            const long pbase = ((long)b * Cdim) * (Hdim * Wdim) + h * Wdim + w;
            #pragma unroll
            for (int nt = 0; nt < 4; nt++) {
                const int c0 = bn + wn + nt * 8 + 2 * tig;
                const long i0 = pbase + (long)c0 * (Hdim * Wdim);
                const long i1 = i0 + (Hdim * Wdim);
                out[i0] = 2.f * (acc[mt][nt][rh * 2]     + bias[c0]     + x[i0]);
                out[i1] = 2.f * (acc[mt][nt][rh * 2 + 1] + bias[c0 + 1] + x[i1]);
            }
        }
    }
}

// ---------------------------------------------------------------------------
extern "C" void kernel_launch(void* const* d_in, const int* in_sizes, int n_in,
                              void* d_out, int out_size) {
    const float* x      = (const float*)d_in[0];
    const float* n1g    = (const float*)d_in[1];
    const float* n1b    = (const float*)d_in[2];
    const float* w_qkv  = (const float*)d_in[3];
    const float* b_qkv  = (const float*)d_in[4];
    const float* w_proj = (const float*)d_in[5];
    const float* b_proj = (const float*)d_in[6];
    float* out = (float*)d_out;

    __nv_bfloat16 *Y, *Obuf, *WTp;
    cudaGetSymbolAddress((void**)&Y,    g_Y);
    cudaGetSymbolAddress((void**)&Obuf, g_O);
    cudaGetSymbolAddress((void**)&WTp,  g_WTp);

    cudaFuncSetAttribute(k23_qkv_attn,
                         cudaFuncAttributeMaxDynamicSharedMemorySize, K23_SMEM);
    const int k4e_smem = 2 * 2 * K4E_STAGE * 2;   // 73728 B per CTA
    cudaFuncSetAttribute(bf16_gemm_proj_epi,
                         cudaFuncAttributeMaxDynamicSharedMemorySize, k4e_smem);

    // W0: weight transpose+convert
    wconv<<<768, 256>>>(w_qkv, w_proj);

    // K1: LN + shift + window partition -> bf16 (packed stores)
    k1_ln_roll_part<<<dim3(4, 128, 8), 256>>>(x, n1g, n1b, Y);

    // K23: persistent fused QKV GEMM + attention with cross-window prefetch
    k23_qkv_attn<<<NSM, 512, K23_SMEM>>>(Y, b_qkv, Obuf);

    // K4E: proj GEMM (BK=64) + fused epilogue
    bf16_gemm_proj_epi<<<dim3(2, 1024), 256, k4e_smem>>>(Obuf, WTp, b_proj, x, out);
}